// round 2
// baseline (speedup 1.0000x reference)
#include <cuda_runtime.h>

#define NN 50000
#define NE 800000
#define HD 128

// ---------------- scratch (__device__ globals: allocation-free) ----------------
__device__ int g_idx64;
__device__ int g_cnt[NN + 1];
__device__ int g_off[NN + 1];
__device__ int g_cur[NN];
__device__ int g_csr[NE];
__device__ __align__(16) float g_z[NN * HD];    // agg output / gemm2 output (reused)
__device__ __align__(16) float g_h1[NN * HD];   // gemm1 output
__device__ __align__(16) float g_h[NN * HD];    // layer-0 output
__device__ float g_sum[2][HD];
__device__ float g_sq[2][HD];
__device__ __align__(16) float g_scale[HD];
__device__ __align__(16) float g_shift[HD];

// ---------------- edge dtype detection (int32 vs int64) ----------------
// Values are in [0, 50000) so if the buffer is int64, every odd 32-bit word
// (the high half) is zero. If int32, odd words are random node ids: the
// probability that 32 of them are all zero is ~(2e-5)^32 ~ 0.
__global__ void k_detect(const unsigned int* __restrict__ w) {
    if (threadIdx.x == 0) {
        int is64 = 1;
        for (int i = 1; i < 64; i += 2)
            if (w[i] != 0u) is64 = 0;
        g_idx64 = is64;
    }
}

__device__ __forceinline__ int edge_at(const void* ei, long long i) {
    return g_idx64 ? (int)((const long long*)ei)[i] : ((const int*)ei)[i];
}

// ---------------- CSR build ----------------
__global__ void k_zero() {
    int i = blockIdx.x * blockDim.x + threadIdx.x;
    if (i <= NN) g_cnt[i] = 0;
    if (i < HD) {
        g_sum[0][i] = 0.f; g_sq[0][i] = 0.f;
        g_sum[1][i] = 0.f; g_sq[1][i] = 0.f;
    }
}

__global__ void k_hist(const void* __restrict__ ei) {
    int e = blockIdx.x * blockDim.x + threadIdx.x;
    if (e < NE) {
        int d = edge_at(ei, (long long)NE + e);
        atomicAdd(&g_cnt[d], 1);
    }
}

__global__ void k_scan() {
    __shared__ int part[1024];
    int t = threadIdx.x;
    const int C = 49;                 // 1024*49 >= 50000
    int b = t * C;
    int e = b + C; if (e > NN) e = NN;
    int s = 0;
    for (int i = b; i < e; i++) s += g_cnt[i];
    part[t] = s;
    __syncthreads();
    for (int d = 1; d < 1024; d <<= 1) {
        int v = (t >= d) ? part[t - d] : 0;
        __syncthreads();
        part[t] += v;
        __syncthreads();
    }
    int run = (t == 0) ? 0 : part[t - 1];
    for (int i = b; i < e; i++) {
        int c = g_cnt[i];
        g_off[i] = run;
        g_cur[i] = run;
        run += c;
    }
    if (t == 1023) g_off[NN] = part[1023];
}

__global__ void k_scatter(const void* __restrict__ ei) {
    int e = blockIdx.x * blockDim.x + threadIdx.x;
    if (e < NE) {
        int d = edge_at(ei, (long long)NE + e);
        int s = edge_at(ei, e);
        int p = atomicAdd(&g_cur[d], 1);
        g_csr[p] = s;
    }
}

// ---------------- aggregation: z[i] = h[i] + sum_{j in N(i)} h[j] ----------------
// One warp per node, float4 lanes (32 lanes * 16B = full 512B row), atomic-free.
__global__ void __launch_bounds__(256) k_agg(const float* __restrict__ h,
                                             float* __restrict__ z) {
    int node = blockIdx.x * 8 + (threadIdx.x >> 5);
    if (node >= NN) return;
    int lane = threadIdx.x & 31;
    const float4* hv = (const float4*)h;
    float4 acc = hv[(size_t)node * 32 + lane];
    int b = g_off[node], e = g_off[node + 1];
    for (int j = b; j < e; j++) {
        int s = g_csr[j];
        float4 v = __ldg(&hv[(size_t)s * 32 + lane]);
        acc.x += v.x; acc.y += v.y; acc.z += v.z; acc.w += v.w;
    }
    ((float4*)z)[(size_t)node * 32 + lane] = acc;
}

// ---------------- GEMM: C = act(A @ W + bias), A: [NN,128], W: [128,128] ----------------
// 128x128 output tile per block, 256 threads, 8x8 microtile per thread.
// Packed fma.rn.f32x2 doubles the FFMA pipe rate.
constexpr int AS       = 129;                 // padded A stride (bank-conflict relief)
constexpr int W_ELE    = HD * HD;             // 16384 floats (64 KB)
constexpr int A_ELE    = HD * AS;             // 16512 floats
constexpr int STAT_OFF = W_ELE + A_ELE;
constexpr int SM_FLOATS = STAT_OFF + 2 * HD;
constexpr size_t SMEM_BYTES = SM_FLOATS * sizeof(float);   // ~130 KB

template <bool RELU>
__global__ void __launch_bounds__(256, 1) k_gemm(const float* __restrict__ A,
                                                 const float* __restrict__ W,
                                                 const float* __restrict__ B,
                                                 float* __restrict__ C,
                                                 int slot) {
    extern __shared__ float sm[];
    float* w_s = sm;                 // w_s[k][n], row-major, matches W layout
    float* a_s = sm + W_ELE;         // a_s[k][row] transposed for broadcast reads
    int tid = threadIdx.x;
    int m0 = blockIdx.x * 128;

    // Load full W tile (coalesced float4)
    const float4* W4 = (const float4*)W;
    float4* ws4 = (float4*)w_s;
    #pragma unroll
    for (int i = tid; i < W_ELE / 4; i += 256) ws4[i] = W4[i];

    // Load A tile transposed (zero-pad past the last row)
    #pragma unroll
    for (int i = tid; i < 128 * 32; i += 256) {
        int row = i >> 5, kq = i & 31;
        float4 v = make_float4(0.f, 0.f, 0.f, 0.f);
        int gr = m0 + row;
        if (gr < NN) v = ((const float4*)(A + (size_t)gr * HD))[kq];
        a_s[(4 * kq + 0) * AS + row] = v.x;
        a_s[(4 * kq + 1) * AS + row] = v.y;
        a_s[(4 * kq + 2) * AS + row] = v.z;
        a_s[(4 * kq + 3) * AS + row] = v.w;
    }
    __syncthreads();

    int cg = tid & 15, rg = tid >> 4;
    int c0 = cg * 8, r0 = rg * 8;

    unsigned long long acc[8][4];
    #pragma unroll
    for (int i = 0; i < 8; i++)
        #pragma unroll
        for (int j = 0; j < 4; j++) acc[i][j] = 0ull;

    #pragma unroll 4
    for (int k = 0; k < 128; k++) {
        const float* ar = a_s + k * AS + r0;
        const unsigned long long* wr =
            (const unsigned long long*)(w_s + k * HD + c0);
        unsigned long long wv[4];
        #pragma unroll
        for (int j = 0; j < 4; j++) wv[j] = wr[j];
        #pragma unroll
        for (int i = 0; i < 8; i++) {
            float av = ar[i];
            unsigned long long ad;
            asm("mov.b64 %0, {%1, %1};" : "=l"(ad) : "f"(av));
            #pragma unroll
            for (int j = 0; j < 4; j++)
                asm("fma.rn.f32x2 %0, %1, %2, %0;"
                    : "+l"(acc[i][j]) : "l"(ad), "l"(wv[j]));
        }
    }

    // Epilogue: bias (+relu or +BN-stat accumulation), store
    float b8[8];
    {
        float4 bb0 = ((const float4*)(B + c0))[0];
        float4 bb1 = ((const float4*)(B + c0))[1];
        b8[0] = bb0.x; b8[1] = bb0.y; b8[2] = bb0.z; b8[3] = bb0.w;
        b8[4] = bb1.x; b8[5] = bb1.y; b8[6] = bb1.z; b8[7] = bb1.w;
    }
    float cs[8], cq[8];
    #pragma unroll
    for (int j = 0; j < 8; j++) { cs[j] = 0.f; cq[j] = 0.f; }

    #pragma unroll
    for (int i = 0; i < 8; i++) {
        int gr = m0 + r0 + i;
        if (gr < NN) {
            float v[8];
            #pragma unroll
            for (int j = 0; j < 4; j++) {
                v[2 * j]     = __uint_as_float((unsigned)(acc[i][j] & 0xffffffffull)) + b8[2 * j];
                v[2 * j + 1] = __uint_as_float((unsigned)(acc[i][j] >> 32)) + b8[2 * j + 1];
            }
            if (RELU) {
                #pragma unroll
                for (int j = 0; j < 8; j++) v[j] = fmaxf(v[j], 0.f);
            } else {
                #pragma unroll
                for (int j = 0; j < 8; j++) { cs[j] += v[j]; cq[j] += v[j] * v[j]; }
            }
            float4* cp = (float4*)(C + (size_t)gr * HD + c0);
            cp[0] = make_float4(v[0], v[1], v[2], v[3]);
            cp[1] = make_float4(v[4], v[5], v[6], v[7]);
        }
    }

    if (!RELU) {
        float* bsum = sm + STAT_OFF;
        float* bsq  = bsum + HD;
        if (tid < HD) { bsum[tid] = 0.f; bsq[tid] = 0.f; }
        __syncthreads();
        #pragma unroll
        for (int j = 0; j < 8; j++) {
            atomicAdd(&bsum[c0 + j], cs[j]);
            atomicAdd(&bsq[c0 + j], cq[j]);
        }
        __syncthreads();
        if (tid < HD) {
            atomicAdd(&g_sum[slot][tid], bsum[tid]);
            atomicAdd(&g_sq[slot][tid], bsq[tid]);
        }
    }
}

// ---------------- BatchNorm ----------------
__global__ void k_bnprep(const float* __restrict__ g,
                         const float* __restrict__ be, int slot) {
    int c = threadIdx.x;
    if (c < HD) {
        float mu  = g_sum[slot][c] * (1.0f / NN);
        float var = g_sq[slot][c] * (1.0f / NN) - mu * mu;
        float sc  = g[c] * rsqrtf(var + 1e-5f);
        g_scale[c] = sc;
        g_shift[c] = be[c] - mu * sc;
    }
}

__global__ void __launch_bounds__(256) k_bnapply(const float* __restrict__ z,
                                                 float* __restrict__ o) {
    int i = blockIdx.x * blockDim.x + threadIdx.x;
    if (i < NN * 32) {
        float4 v = ((const float4*)z)[i];
        int q = i & 31;
        float4 sc = ((const float4*)g_scale)[q];
        float4 sh = ((const float4*)g_shift)[q];
        v.x = fmaxf(fmaf(v.x, sc.x, sh.x), 0.f);
        v.y = fmaxf(fmaf(v.y, sc.y, sh.y), 0.f);
        v.z = fmaxf(fmaf(v.z, sc.z, sh.z), 0.f);
        v.w = fmaxf(fmaf(v.w, sc.w, sh.w), 0.f);
        ((float4*)o)[i] = v;
    }
}

// ---------------- launcher ----------------
extern "C" void kernel_launch(void* const* d_in, const int* in_sizes, int n_in,
                              void* d_out, int out_size) {
    (void)in_sizes; (void)n_in; (void)out_size;
    const float* x    = (const float*)d_in[0];
    const void*  ei   = d_in[1];
    const float* w1_0 = (const float*)d_in[2];
    const float* b1_0 = (const float*)d_in[3];
    const float* w2_0 = (const float*)d_in[4];
    const float* b2_0 = (const float*)d_in[5];
    const float* g_0  = (const float*)d_in[6];
    const float* be_0 = (const float*)d_in[7];
    const float* w1_1 = (const float*)d_in[8];
    const float* b1_1 = (const float*)d_in[9];
    const float* w2_1 = (const float*)d_in[10];
    const float* b2_1 = (const float*)d_in[11];
    const float* g_1  = (const float*)d_in[12];
    const float* be_1 = (const float*)d_in[13];
    float* out = (float*)d_out;

    float *zp, *h1p, *hp;
    cudaGetSymbolAddress((void**)&zp,  g_z);
    cudaGetSymbolAddress((void**)&h1p, g_h1);
    cudaGetSymbolAddress((void**)&hp,  g_h);

    cudaFuncSetAttribute(k_gemm<true>,  cudaFuncAttributeMaxDynamicSharedMemorySize, (int)SMEM_BYTES);
    cudaFuncSetAttribute(k_gemm<false>, cudaFuncAttributeMaxDynamicSharedMemorySize, (int)SMEM_BYTES);

    // CSR build (edges are identical across both layers)
    k_detect<<<1, 32>>>((const unsigned int*)ei);
    k_zero<<<(NN + 1 + 255) / 256, 256>>>();
    k_hist<<<(NE + 255) / 256, 256>>>(ei);
    k_scan<<<1, 1024>>>();
    k_scatter<<<(NE + 255) / 256, 256>>>(ei);

    const int gblocks = (NN + 127) / 128;   // 391

    // Layer 0
    k_agg<<<(NN + 7) / 8, 256>>>(x, zp);
    k_gemm<true ><<<gblocks, 256, SMEM_BYTES>>>(zp,  w1_0, b1_0, h1p, 0);
    k_gemm<false><<<gblocks, 256, SMEM_BYTES>>>(h1p, w2_0, b2_0, zp,  0);
    k_bnprep<<<1, 128>>>(g_0, be_0, 0);
    k_bnapply<<<(NN * 32 + 255) / 256, 256>>>(zp, hp);

    // Layer 1
    k_agg<<<(NN + 7) / 8, 256>>>(hp, zp);
    k_gemm<true ><<<gblocks, 256, SMEM_BYTES>>>(zp,  w1_1, b1_1, h1p, 1);
    k_gemm<false><<<gblocks, 256, SMEM_BYTES>>>(h1p, w2_1, b2_1, zp,  1);
    k_bnprep<<<1, 128>>>(g_1, be_1, 1);
    k_bnapply<<<(NN * 32 + 255) / 256, 256>>>(zp, out);
}

// round 3
// speedup vs baseline: 1.2343x; 1.2343x over previous
#include <cuda_runtime.h>

#define NN 50000
#define NE 800000
#define HD 128
#define SCAN_B 256
#define NBLK ((NN + SCAN_B - 1) / SCAN_B)   // 196

// ---------------- scratch (__device__ globals: allocation-free) ----------------
__device__ int g_idx64;
__device__ int g_cnt[NN + 1];
__device__ int g_off[NN + 1];
__device__ int g_cur[NN];
__device__ int g_csr[NE];
__device__ int g_part[NBLK];
__device__ int g_partpre[NBLK];
__device__ __align__(16) float g_z[NN * HD];    // agg output / gemm2 output (reused)
__device__ __align__(16) float g_h1[NN * HD];   // gemm1 output
__device__ __align__(16) float g_h[NN * HD];    // layer-0 output
__device__ float g_sum[2][HD];
__device__ float g_sq[2][HD];
__device__ __align__(16) float g_scale[HD];
__device__ __align__(16) float g_shift[HD];

// ---------------- edge dtype detection (int32 vs int64) ----------------
// Values are in [0, 50000) so if the buffer is int64, every odd 32-bit word
// (the high half) is zero. If int32, odd words are random node ids: the
// probability that 32 of them are all zero is ~(2e-5)^32 ~ 0.
__global__ void k_detect(const unsigned int* __restrict__ w) {
    if (threadIdx.x == 0) {
        int is64 = 1;
        for (int i = 1; i < 64; i += 2)
            if (w[i] != 0u) is64 = 0;
        g_idx64 = is64;
    }
}

__device__ __forceinline__ int edge_at(const void* ei, long long i) {
    return g_idx64 ? (int)((const long long*)ei)[i] : ((const int*)ei)[i];
}

// ---------------- CSR build ----------------
__global__ void k_zero() {
    int i = blockIdx.x * blockDim.x + threadIdx.x;
    if (i <= NN) g_cnt[i] = 0;
    if (i < HD) {
        g_sum[0][i] = 0.f; g_sq[0][i] = 0.f;
        g_sum[1][i] = 0.f; g_sq[1][i] = 0.f;
    }
}

__global__ void k_hist(const void* __restrict__ ei) {
    int e = blockIdx.x * blockDim.x + threadIdx.x;
    if (e < NE) {
        int d = edge_at(ei, (long long)NE + e);
        atomicAdd(&g_cnt[d], 1);
    }
}

// Distributed 3-stage scan (replaces the single-block k_scan that burned 77us
// at the 1.82cyc/LDG single-SM LSU floor).
__global__ void k_blocksum() {
    __shared__ int red[SCAN_B];
    int t = threadIdx.x;
    int i = blockIdx.x * SCAN_B + t;
    red[t] = (i < NN) ? g_cnt[i] : 0;
    __syncthreads();
    #pragma unroll
    for (int d = SCAN_B / 2; d > 0; d >>= 1) {
        if (t < d) red[t] += red[t + d];
        __syncthreads();
    }
    if (t == 0) g_part[blockIdx.x] = red[0];
}

__global__ void k_scanpart() {
    __shared__ int s[SCAN_B];
    int t = threadIdx.x;
    int v = (t < NBLK) ? g_part[t] : 0;
    s[t] = v;
    __syncthreads();
    #pragma unroll
    for (int d = 1; d < SCAN_B; d <<= 1) {
        int u = (t >= d) ? s[t - d] : 0;
        __syncthreads();
        s[t] += u;
        __syncthreads();
    }
    if (t < NBLK) g_partpre[t] = s[t] - v;   // exclusive prefix of block sums
    if (t == 0) g_off[NN] = NE;              // total is a compile-time constant
}

__global__ void k_offsets() {
    __shared__ int s[SCAN_B];
    int t = threadIdx.x;
    int i = blockIdx.x * SCAN_B + t;
    int v = (i < NN) ? g_cnt[i] : 0;
    s[t] = v;
    __syncthreads();
    #pragma unroll
    for (int d = 1; d < SCAN_B; d <<= 1) {
        int u = (t >= d) ? s[t - d] : 0;
        __syncthreads();
        s[t] += u;
        __syncthreads();
    }
    if (i < NN) {
        int o = g_partpre[blockIdx.x] + s[t] - v;   // exclusive
        g_off[i] = o;
        g_cur[i] = o;
    }
}

__global__ void k_scatter(const void* __restrict__ ei) {
    int e = blockIdx.x * blockDim.x + threadIdx.x;
    if (e < NE) {
        int d = edge_at(ei, (long long)NE + e);
        int s = edge_at(ei, e);
        int p = atomicAdd(&g_cur[d], 1);
        g_csr[p] = s;
    }
}

// ---------------- aggregation: z[i] = h[i] + sum_{j in N(i)} h[j] ----------------
// One warp per node, float4 lanes (32 lanes * 16B = full 512B row), atomic-free.
__global__ void __launch_bounds__(256) k_agg(const float* __restrict__ h,
                                             float* __restrict__ z) {
    int node = blockIdx.x * 8 + (threadIdx.x >> 5);
    if (node >= NN) return;
    int lane = threadIdx.x & 31;
    const float4* hv = (const float4*)h;
    float4 acc = hv[(size_t)node * 32 + lane];
    int b = g_off[node], e = g_off[node + 1];
    for (int j = b; j < e; j++) {
        int s = g_csr[j];
        float4 v = __ldg(&hv[(size_t)s * 32 + lane]);
        acc.x += v.x; acc.y += v.y; acc.z += v.z; acc.w += v.w;
    }
    ((float4*)z)[(size_t)node * 32 + lane] = acc;
}

// ---------------- GEMM: C = act(A @ W + bias), A: [NN,128], W: [128,128] ----------------
// 128x128 output tile per block, 256 threads, 8x8 microtile per thread.
// Packed fma.rn.f32x2 doubles the FFMA pipe rate.
constexpr int AS       = 129;                 // padded A stride (bank-conflict relief)
constexpr int W_ELE    = HD * HD;             // 16384 floats (64 KB)
constexpr int A_ELE    = HD * AS;             // 16512 floats
constexpr int STAT_OFF = W_ELE + A_ELE;
constexpr int SM_FLOATS = STAT_OFF + 2 * HD;
constexpr size_t SMEM_BYTES = SM_FLOATS * sizeof(float);   // ~130 KB

template <bool RELU>
__global__ void __launch_bounds__(256, 1) k_gemm(const float* __restrict__ A,
                                                 const float* __restrict__ W,
                                                 const float* __restrict__ B,
                                                 float* __restrict__ C,
                                                 int slot) {
    extern __shared__ float sm[];
    float* w_s = sm;                 // w_s[k][n], row-major, matches W layout
    float* a_s = sm + W_ELE;         // a_s[k][row] transposed for broadcast reads
    int tid = threadIdx.x;
    int m0 = blockIdx.x * 128;

    // Load full W tile (coalesced float4)
    const float4* W4 = (const float4*)W;
    float4* ws4 = (float4*)w_s;
    #pragma unroll
    for (int i = tid; i < W_ELE / 4; i += 256) ws4[i] = W4[i];

    // Load A tile transposed (zero-pad past the last row)
    #pragma unroll
    for (int i = tid; i < 128 * 32; i += 256) {
        int row = i >> 5, kq = i & 31;
        float4 v = make_float4(0.f, 0.f, 0.f, 0.f);
        int gr = m0 + row;
        if (gr < NN) v = ((const float4*)(A + (size_t)gr * HD))[kq];
        a_s[(4 * kq + 0) * AS + row] = v.x;
        a_s[(4 * kq + 1) * AS + row] = v.y;
        a_s[(4 * kq + 2) * AS + row] = v.z;
        a_s[(4 * kq + 3) * AS + row] = v.w;
    }
    __syncthreads();

    int cg = tid & 15, rg = tid >> 4;
    int c0 = cg * 8, r0 = rg * 8;

    unsigned long long acc[8][4];
    #pragma unroll
    for (int i = 0; i < 8; i++)
        #pragma unroll
        for (int j = 0; j < 4; j++) acc[i][j] = 0ull;

    #pragma unroll 4
    for (int k = 0; k < 128; k++) {
        const float* ar = a_s + k * AS + r0;
        const unsigned long long* wr =
            (const unsigned long long*)(w_s + k * HD + c0);
        unsigned long long wv[4];
        #pragma unroll
        for (int j = 0; j < 4; j++) wv[j] = wr[j];
        #pragma unroll
        for (int i = 0; i < 8; i++) {
            float av = ar[i];
            unsigned long long ad;
            asm("mov.b64 %0, {%1, %1};" : "=l"(ad) : "f"(av));
            #pragma unroll
            for (int j = 0; j < 4; j++)
                asm("fma.rn.f32x2 %0, %1, %2, %0;"
                    : "+l"(acc[i][j]) : "l"(ad), "l"(wv[j]));
        }
    }

    // Epilogue: bias (+relu or +BN-stat accumulation), store
    float b8[8];
    {
        float4 bb0 = ((const float4*)(B + c0))[0];
        float4 bb1 = ((const float4*)(B + c0))[1];
        b8[0] = bb0.x; b8[1] = bb0.y; b8[2] = bb0.z; b8[3] = bb0.w;
        b8[4] = bb1.x; b8[5] = bb1.y; b8[6] = bb1.z; b8[7] = bb1.w;
    }
    float cs[8], cq[8];
    #pragma unroll
    for (int j = 0; j < 8; j++) { cs[j] = 0.f; cq[j] = 0.f; }

    #pragma unroll
    for (int i = 0; i < 8; i++) {
        int gr = m0 + r0 + i;
        if (gr < NN) {
            float v[8];
            #pragma unroll
            for (int j = 0; j < 4; j++) {
                v[2 * j]     = __uint_as_float((unsigned)(acc[i][j] & 0xffffffffull)) + b8[2 * j];
                v[2 * j + 1] = __uint_as_float((unsigned)(acc[i][j] >> 32)) + b8[2 * j + 1];
            }
            if (RELU) {
                #pragma unroll
                for (int j = 0; j < 8; j++) v[j] = fmaxf(v[j], 0.f);
            } else {
                #pragma unroll
                for (int j = 0; j < 8; j++) { cs[j] += v[j]; cq[j] += v[j] * v[j]; }
            }
            float4* cp = (float4*)(C + (size_t)gr * HD + c0);
            cp[0] = make_float4(v[0], v[1], v[2], v[3]);
            cp[1] = make_float4(v[4], v[5], v[6], v[7]);
        }
    }

    if (!RELU) {
        float* bsum = sm + STAT_OFF;
        float* bsq  = bsum + HD;
        if (tid < HD) { bsum[tid] = 0.f; bsq[tid] = 0.f; }
        __syncthreads();
        #pragma unroll
        for (int j = 0; j < 8; j++) {
            atomicAdd(&bsum[c0 + j], cs[j]);
            atomicAdd(&bsq[c0 + j], cq[j]);
        }
        __syncthreads();
        if (tid < HD) {
            atomicAdd(&g_sum[slot][tid], bsum[tid]);
            atomicAdd(&g_sq[slot][tid], bsq[tid]);
        }
    }
}

// ---------------- BatchNorm ----------------
__global__ void k_bnprep(const float* __restrict__ g,
                         const float* __restrict__ be, int slot) {
    int c = threadIdx.x;
    if (c < HD) {
        float mu  = g_sum[slot][c] * (1.0f / NN);
        float var = g_sq[slot][c] * (1.0f / NN) - mu * mu;
        float sc  = g[c] * rsqrtf(var + 1e-5f);
        g_scale[c] = sc;
        g_shift[c] = be[c] - mu * sc;
    }
}

__global__ void __launch_bounds__(256) k_bnapply(const float* __restrict__ z,
                                                 float* __restrict__ o) {
    int i = blockIdx.x * blockDim.x + threadIdx.x;
    if (i < NN * 32) {
        float4 v = ((const float4*)z)[i];
        int q = i & 31;
        float4 sc = ((const float4*)g_scale)[q];
        float4 sh = ((const float4*)g_shift)[q];
        v.x = fmaxf(fmaf(v.x, sc.x, sh.x), 0.f);
        v.y = fmaxf(fmaf(v.y, sc.y, sh.y), 0.f);
        v.z = fmaxf(fmaf(v.z, sc.z, sh.z), 0.f);
        v.w = fmaxf(fmaf(v.w, sc.w, sh.w), 0.f);
        ((float4*)o)[i] = v;
    }
}

// ---------------- launcher ----------------
extern "C" void kernel_launch(void* const* d_in, const int* in_sizes, int n_in,
                              void* d_out, int out_size) {
    (void)in_sizes; (void)n_in; (void)out_size;
    const float* x    = (const float*)d_in[0];
    const void*  ei   = d_in[1];
    const float* w1_0 = (const float*)d_in[2];
    const float* b1_0 = (const float*)d_in[3];
    const float* w2_0 = (const float*)d_in[4];
    const float* b2_0 = (const float*)d_in[5];
    const float* g_0  = (const float*)d_in[6];
    const float* be_0 = (const float*)d_in[7];
    const float* w1_1 = (const float*)d_in[8];
    const float* b1_1 = (const float*)d_in[9];
    const float* w2_1 = (const float*)d_in[10];
    const float* b2_1 = (const float*)d_in[11];
    const float* g_1  = (const float*)d_in[12];
    const float* be_1 = (const float*)d_in[13];
    float* out = (float*)d_out;

    float *zp, *h1p, *hp;
    cudaGetSymbolAddress((void**)&zp,  g_z);
    cudaGetSymbolAddress((void**)&h1p, g_h1);
    cudaGetSymbolAddress((void**)&hp,  g_h);

    cudaFuncSetAttribute(k_gemm<true>,  cudaFuncAttributeMaxDynamicSharedMemorySize, (int)SMEM_BYTES);
    cudaFuncSetAttribute(k_gemm<false>, cudaFuncAttributeMaxDynamicSharedMemorySize, (int)SMEM_BYTES);

    // CSR build (edges are identical across both layers)
    k_detect<<<1, 32>>>((const unsigned int*)ei);
    k_zero<<<(NN + 1 + 255) / 256, 256>>>();
    k_hist<<<(NE + 255) / 256, 256>>>(ei);
    k_blocksum<<<NBLK, SCAN_B>>>();
    k_scanpart<<<1, SCAN_B>>>();
    k_offsets<<<NBLK, SCAN_B>>>();
    k_scatter<<<(NE + 255) / 256, 256>>>(ei);

    const int gblocks = (NN + 127) / 128;   // 391

    // Layer 0
    k_agg<<<(NN + 7) / 8, 256>>>(x, zp);
    k_gemm<true ><<<gblocks, 256, SMEM_BYTES>>>(zp,  w1_0, b1_0, h1p, 0);
    k_gemm<false><<<gblocks, 256, SMEM_BYTES>>>(h1p, w2_0, b2_0, zp,  0);
    k_bnprep<<<1, 128>>>(g_0, be_0, 0);
    k_bnapply<<<(NN * 32 + 255) / 256, 256>>>(zp, hp);

    // Layer 1
    k_agg<<<(NN + 7) / 8, 256>>>(hp, zp);
    k_gemm<true ><<<gblocks, 256, SMEM_BYTES>>>(zp,  w1_1, b1_1, h1p, 1);
    k_gemm<false><<<gblocks, 256, SMEM_BYTES>>>(h1p, w2_1, b2_1, zp,  1);
    k_bnprep<<<1, 128>>>(g_1, be_1, 1);
    k_bnapply<<<(NN * 32 + 255) / 256, 256>>>(zp, out);
}